// round 1
// baseline (speedup 1.0000x reference)
#include <cuda_runtime.h>
#include <math.h>

#define M_ROWS 16384
#define K1 1024
#define N1 512
#define NANC 9
#define NBOX (M_ROWS*NANC)          /* 147456 */
#define NOUT 45
#define PRE_NMS 6000
#define POST_NMS 300
#define IOU_THR 0.7f
#define REG_OFF (M_ROWS*NANC)            /* 147456 */
#define PROP_OFF (REG_OFF + M_ROWS*NANC*4) /* 737280 */

// ---------------- scratch (device globals; no allocation) ----------------
__device__ float g_h[M_ROWS*N1];            // bottleneck activations (32MB)
__device__ float g_boxes[NBOX*4];           // decoded+clipped boxes
__device__ unsigned long long g_keys[NBOX]; // (score_bits<<32)|~idx
__device__ float g_cboxes[PRE_NMS*4];
__device__ unsigned long long g_ckeys[PRE_NMS];
__device__ unsigned int g_hist[256];
__device__ unsigned long long g_prefix;
__device__ int g_krem;
__device__ int g_count;

// ---------------- kernel 1: bottleneck GEMM + bias + relu ----------------
// C[16384,512] = relu(A[16384,1024] @ W[1024,512] + b)
// 128x128 block tile, BK=8, 256 threads, 8x8 per thread.
__global__ __launch_bounds__(256, 2)
void gemm_bneck(const float* __restrict__ A, const float* __restrict__ W,
                const float* __restrict__ bias) {
    __shared__ float As[8][128];
    __shared__ float Bs[8][128];
    const int bx = blockIdx.x;            // 0..3  (N tiles)
    const int by = blockIdx.y;            // 0..127 (M tiles)
    const int tid = threadIdx.x;
    const int tx = tid & 15;
    const int ty = tid >> 4;
    const int m0 = by * 128, n0 = bx * 128;

    const int arow = tid >> 1;            // 0..127
    const int acol = (tid & 1) * 4;       // 0 or 4
    const int brow = tid >> 5;            // 0..7
    const int bcol = (tid & 31) * 4;

    const float* Aptr = A + (size_t)(m0 + arow) * K1 + acol;
    const float* Wptr = W + (size_t)brow * N1 + n0 + bcol;

    float acc[8][8];
#pragma unroll
    for (int i = 0; i < 8; i++)
#pragma unroll
        for (int j = 0; j < 8; j++) acc[i][j] = 0.f;

    for (int k0 = 0; k0 < K1; k0 += 8) {
        float4 a = *(const float4*)(Aptr + k0);
        float4 b = *(const float4*)(Wptr + (size_t)k0 * N1);
        As[acol + 0][arow] = a.x;
        As[acol + 1][arow] = a.y;
        As[acol + 2][arow] = a.z;
        As[acol + 3][arow] = a.w;
        *(float4*)&Bs[brow][bcol] = b;
        __syncthreads();
#pragma unroll
        for (int k = 0; k < 8; k++) {
            float ra[8], rb[8];
            *(float4*)&ra[0] = *(const float4*)&As[k][ty * 8];
            *(float4*)&ra[4] = *(const float4*)&As[k][ty * 8 + 4];
            *(float4*)&rb[0] = *(const float4*)&Bs[k][tx * 8];
            *(float4*)&rb[4] = *(const float4*)&Bs[k][tx * 8 + 4];
#pragma unroll
            for (int i = 0; i < 8; i++)
#pragma unroll
                for (int j = 0; j < 8; j++) acc[i][j] += ra[i] * rb[j];
        }
        __syncthreads();
    }
    float bb[8];
    *(float4*)&bb[0] = *(const float4*)&bias[n0 + tx * 8];
    *(float4*)&bb[4] = *(const float4*)&bias[n0 + tx * 8 + 4];
#pragma unroll
    for (int i = 0; i < 8; i++) {
        const int m = m0 + ty * 8 + i;
        float4 o0, o1;
        o0.x = fmaxf(acc[i][0] + bb[0], 0.f);
        o0.y = fmaxf(acc[i][1] + bb[1], 0.f);
        o0.z = fmaxf(acc[i][2] + bb[2], 0.f);
        o0.w = fmaxf(acc[i][3] + bb[3], 0.f);
        o1.x = fmaxf(acc[i][4] + bb[4], 0.f);
        o1.y = fmaxf(acc[i][5] + bb[5], 0.f);
        o1.z = fmaxf(acc[i][6] + bb[6], 0.f);
        o1.w = fmaxf(acc[i][7] + bb[7], 0.f);
        *(float4*)&g_h[(size_t)m * N1 + n0 + tx * 8]     = o0;
        *(float4*)&g_h[(size_t)m * N1 + n0 + tx * 8 + 4] = o1;
    }
}

// ---------------- kernel 2: head GEMM + sigmoid + box decode ----------------
// out45[64 rows, 45 cols] per block; K=512, BK=32, 256 threads, 4x3 per thread.
__global__ __launch_bounds__(256, 4)
void head_kernel(const float* __restrict__ ancs,
                 const float* __restrict__ wc, const float* __restrict__ bc,
                 const float* __restrict__ wr, const float* __restrict__ br,
                 float* __restrict__ out) {
    __shared__ float Hs[32][64];
    __shared__ float Ws[32][48];
    __shared__ float Os[64][48];
    const int tid = threadIdx.x;
    const int tx = tid & 15;      // col group
    const int ty = tid >> 4;      // row group
    const int gr0 = blockIdx.x * 64;

    float acc[4][3];
#pragma unroll
    for (int i = 0; i < 4; i++)
#pragma unroll
        for (int j = 0; j < 3; j++) acc[i][j] = 0.f;

    for (int k0 = 0; k0 < N1; k0 += 32) {
        // load H tile [64 rows x 32 k] transposed into Hs[k][m]
#pragma unroll
        for (int v = 0; v < 2; v++) {
            int lin = tid * 8 + v * 4;
            int r = lin >> 5;
            int c = lin & 31;
            float4 h4 = *(const float4*)&g_h[(size_t)(gr0 + r) * N1 + k0 + c];
            Hs[c + 0][r] = h4.x; Hs[c + 1][r] = h4.y;
            Hs[c + 2][r] = h4.z; Hs[c + 3][r] = h4.w;
        }
        // load W tile [32 k x 48 cols]
        for (int idx = tid; idx < 32 * 48; idx += 256) {
            int r = idx / 48, o = idx % 48;
            float v = 0.f;
            if (o < 9)       v = wc[(size_t)(k0 + r) * 9 + o];
            else if (o < 45) v = wr[(size_t)(k0 + r) * 36 + (o - 9)];
            Ws[r][o] = v;
        }
        __syncthreads();
#pragma unroll
        for (int k = 0; k < 32; k++) {
            float a0 = Hs[k][ty * 4 + 0], a1 = Hs[k][ty * 4 + 1];
            float a2 = Hs[k][ty * 4 + 2], a3 = Hs[k][ty * 4 + 3];
            float b0 = Ws[k][tx * 3 + 0], b1 = Ws[k][tx * 3 + 1], b2 = Ws[k][tx * 3 + 2];
            acc[0][0] += a0 * b0; acc[0][1] += a0 * b1; acc[0][2] += a0 * b2;
            acc[1][0] += a1 * b0; acc[1][1] += a1 * b1; acc[1][2] += a1 * b2;
            acc[2][0] += a2 * b0; acc[2][1] += a2 * b1; acc[2][2] += a2 * b2;
            acc[3][0] += a3 * b0; acc[3][1] += a3 * b1; acc[3][2] += a3 * b2;
        }
        __syncthreads();
    }
    // bias + stash in shared
#pragma unroll
    for (int i = 0; i < 4; i++)
#pragma unroll
        for (int j = 0; j < 3; j++) {
            int o = tx * 3 + j;
            float bia = (o < 9) ? bc[o] : ((o < 45) ? br[o - 9] : 0.f);
            Os[ty * 4 + i][o] = acc[i][j] + bia;
        }
    __syncthreads();
    // write cls (sigmoid) and reg
    for (int idx = tid; idx < 64 * 45; idx += 256) {
        int r = idx / 45, o = idx % 45;
        float v = Os[r][o];
        int grow = gr0 + r;
        if (o < 9) out[(size_t)grow * 9 + o] = 1.f / (1.f + expf(-v));
        else       out[REG_OFF + (size_t)grow * 36 + (o - 9)] = v;
    }
    // decode boxes + build keys
    for (int t = tid; t < 64 * 9; t += 256) {
        int r = t / 9, a = t % 9;
        int gi = (gr0 + r) * 9 + a;
        float logit = Os[r][a];
        float score = 1.f / (1.f + expf(-logit));
        float tx_ = Os[r][9 + a * 4 + 0];
        float ty_ = Os[r][9 + a * 4 + 1];
        float tw_ = Os[r][9 + a * 4 + 2];
        float th_ = Os[r][9 + a * 4 + 3];
        float acx = ancs[(size_t)gi * 4 + 0];
        float acy = ancs[(size_t)gi * 4 + 1];
        float aw  = ancs[(size_t)gi * 4 + 2];
        float ah  = ancs[(size_t)gi * 4 + 3];
        float cx = acx + tx_ * aw;
        float cy = acy + ty_ * ah;
        float ww = aw * expf(tw_);
        float hh = ah * expf(th_);
        float x1 = fminf(fmaxf(cx - ww * 0.5f, 0.f), 1.f);
        float y1 = fminf(fmaxf(cy - hh * 0.5f, 0.f), 1.f);
        float x2 = fminf(fmaxf(cx + ww * 0.5f, 0.f), 1.f);
        float y2 = fminf(fmaxf(cy + hh * 0.5f, 0.f), 1.f);
        g_boxes[(size_t)gi * 4 + 0] = x1;
        g_boxes[(size_t)gi * 4 + 1] = y1;
        g_boxes[(size_t)gi * 4 + 2] = x2;
        g_boxes[(size_t)gi * 4 + 3] = y2;
        unsigned sb = __float_as_uint(score);     // score>0 -> monotone bits
        g_keys[gi] = ((unsigned long long)sb << 32) | (unsigned long long)(~(unsigned)gi);
    }
}

// ---------------- selection: exact 64-bit radix select (top-6000) ----------------
__global__ void sel_init() {
    int t = threadIdx.x;
    g_hist[t] = 0u;
    if (t == 0) { g_prefix = 0ull; g_krem = PRE_NMS; g_count = 0; }
}

__global__ void hist_pass(int shift) {
    __shared__ unsigned int sh[256];
    sh[threadIdx.x] = 0u;
    __syncthreads();
    unsigned long long pref = g_prefix;
    unsigned long long mask = (shift == 56) ? 0ull : (~0ull << (shift + 8));
    for (int i = blockIdx.x * blockDim.x + threadIdx.x; i < NBOX; i += gridDim.x * blockDim.x) {
        unsigned long long k = g_keys[i];
        if (((k ^ pref) & mask) == 0ull)
            atomicAdd(&sh[(unsigned)(k >> shift) & 255u], 1u);
    }
    __syncthreads();
    if (sh[threadIdx.x]) atomicAdd(&g_hist[threadIdx.x], sh[threadIdx.x]);
}

__global__ void scan_pass(int shift) {
    int k = g_krem;
    int b = 255;
    for (; b >= 0; --b) {
        int c = (int)g_hist[b];
        if (c >= k) break;
        k -= c;
    }
    if (b < 0) b = 0;
    g_prefix |= ((unsigned long long)(unsigned)b) << shift;
    g_krem = k;
    for (int i = 0; i < 256; i++) g_hist[i] = 0u;
}

__global__ void compact_kernel() {
    unsigned long long thr = g_prefix;   // exact 6000th-largest key
    for (int i = blockIdx.x * blockDim.x + threadIdx.x; i < NBOX; i += gridDim.x * blockDim.x) {
        unsigned long long k = g_keys[i];
        if (k >= thr) {
            int pos = atomicAdd(&g_count, 1);
            if (pos < PRE_NMS) {
                g_ckeys[pos] = k;
                g_cboxes[(size_t)pos * 4 + 0] = g_boxes[(size_t)i * 4 + 0];
                g_cboxes[(size_t)pos * 4 + 1] = g_boxes[(size_t)i * 4 + 1];
                g_cboxes[(size_t)pos * 4 + 2] = g_boxes[(size_t)i * 4 + 2];
                g_cboxes[(size_t)pos * 4 + 3] = g_boxes[(size_t)i * 4 + 3];
            }
        }
    }
}

// ---------------- NMS: single block, boxes resident in SMEM ----------------
__global__ __launch_bounds__(1024)
void nms_kernel(float* __restrict__ out) {
    extern __shared__ unsigned char smem[];
    unsigned long long* s_key = (unsigned long long*)smem;          // 48000B
    float* s_x1 = (float*)(smem + 48000);
    float* s_y1 = (float*)(smem + 48000 + 24000);
    float* s_x2 = (float*)(smem + 48000 + 48000);
    float* s_y2 = (float*)(smem + 48000 + 72000);
    float* s_ar = (float*)(smem + 48000 + 96000);

    __shared__ unsigned long long s_rk[32];
    __shared__ int s_ri[32];
    __shared__ int s_widx;
    __shared__ unsigned long long s_wkey;

    const int tid = threadIdx.x;
    const int lane = tid & 31;
    const int wid = tid >> 5;
    const int nvalid = min(g_count, PRE_NMS);

    for (int i = tid; i < PRE_NMS; i += 1024) {
        if (i < nvalid) {
            s_key[i] = g_ckeys[i];
            float x1 = g_cboxes[(size_t)i * 4 + 0];
            float y1 = g_cboxes[(size_t)i * 4 + 1];
            float x2 = g_cboxes[(size_t)i * 4 + 2];
            float y2 = g_cboxes[(size_t)i * 4 + 3];
            s_x1[i] = x1; s_y1[i] = y1; s_x2[i] = x2; s_y2[i] = y2;
            s_ar[i] = (x2 - x1) * (y2 - y1);
        } else {
            s_key[i] = 0ull;
            s_x1[i] = 0.f; s_y1[i] = 0.f; s_x2[i] = 0.f; s_y2[i] = 0.f; s_ar[i] = 0.f;
        }
    }
    __syncthreads();

    for (int it = 0; it < POST_NMS; it++) {
        // block argmax over keys
        unsigned long long bk = 0ull; int bi = -1;
        for (int i = tid; i < PRE_NMS; i += 1024) {
            unsigned long long k = s_key[i];
            if (k > bk) { bk = k; bi = i; }
        }
#pragma unroll
        for (int off = 16; off > 0; off >>= 1) {
            unsigned long long ok = __shfl_down_sync(0xffffffffu, bk, off);
            int oi = __shfl_down_sync(0xffffffffu, bi, off);
            if (ok > bk) { bk = ok; bi = oi; }
        }
        if (lane == 0) { s_rk[wid] = bk; s_ri[wid] = bi; }
        __syncthreads();
        if (wid == 0) {
            bk = s_rk[lane]; bi = s_ri[lane];
#pragma unroll
            for (int off = 16; off > 0; off >>= 1) {
                unsigned long long ok = __shfl_down_sync(0xffffffffu, bk, off);
                int oi = __shfl_down_sync(0xffffffffu, bi, off);
                if (ok > bk) { bk = ok; bi = oi; }
            }
            if (lane == 0) { s_widx = bi; s_wkey = bk; }
        }
        __syncthreads();

        if (s_wkey == 0ull) {
            if (tid == 0) {
                out[PROP_OFF + it * 4 + 0] = 0.f;
                out[PROP_OFF + it * 4 + 1] = 0.f;
                out[PROP_OFF + it * 4 + 2] = 0.f;
                out[PROP_OFF + it * 4 + 3] = 0.f;
            }
            __syncthreads();
            continue;
        }
        const int w = s_widx;
        const float wx1 = s_x1[w], wy1 = s_y1[w], wx2 = s_x2[w], wy2 = s_y2[w];
        const float wa = s_ar[w];
        if (tid == 0) {
            out[PROP_OFF + it * 4 + 0] = wx1;
            out[PROP_OFF + it * 4 + 1] = wy1;
            out[PROP_OFF + it * 4 + 2] = wx2;
            out[PROP_OFF + it * 4 + 3] = wy2;
            s_key[w] = 0ull;
        }
        for (int i = tid; i < PRE_NMS; i += 1024) {
            unsigned long long k = s_key[i];
            if (k != 0ull) {
                float iw = fminf(wx2, s_x2[i]) - fmaxf(wx1, s_x1[i]);
                float ih = fminf(wy2, s_y2[i]) - fmaxf(wy1, s_y1[i]);
                iw = fmaxf(iw, 0.f);
                ih = fmaxf(ih, 0.f);
                float inter = iw * ih;
                float uni = wa + s_ar[i] - inter;
                float iou = (uni > 0.f) ? inter / uni : 0.f;
                if (iou > IOU_THR) s_key[i] = 0ull;
            }
        }
        __syncthreads();
    }
}

// ---------------- launcher ----------------
extern "C" void kernel_launch(void* const* d_in, const int* in_sizes, int n_in,
                              void* d_out, int out_size) {
    const float* feats   = (const float*)d_in[0];
    const float* ancs    = (const float*)d_in[1];
    /* ancs_valid d_in[2] unused by reference */
    const float* w_bneck = (const float*)d_in[3];
    const float* b_bneck = (const float*)d_in[4];
    const float* w_cls   = (const float*)d_in[5];
    const float* b_cls   = (const float*)d_in[6];
    const float* w_reg   = (const float*)d_in[7];
    const float* b_reg   = (const float*)d_in[8];
    float* out = (float*)d_out;

    cudaFuncSetAttribute(nms_kernel, cudaFuncAttributeMaxDynamicSharedMemorySize, 168000);

    gemm_bneck<<<dim3(4, 128), 256>>>(feats, w_bneck, b_bneck);
    head_kernel<<<M_ROWS / 64, 256>>>(ancs, w_cls, b_cls, w_reg, b_reg, out);
    sel_init<<<1, 256>>>();
    for (int p = 7; p >= 0; --p) {
        hist_pass<<<288, 256>>>(p * 8);
        scan_pass<<<1, 1>>>(p * 8);
    }
    compact_kernel<<<288, 256>>>();
    nms_kernel<<<1, 1024, 168000>>>(out);
}

// round 2
// speedup vs baseline: 1.0003x; 1.0003x over previous
#include <cuda_runtime.h>
#include <math.h>

#define M_ROWS 16384
#define K1 1024
#define N1 512
#define NANC 9
#define NBOX (M_ROWS*NANC)          /* 147456 */
#define NOUT 45
#define PRE_NMS 6000
#define POST_NMS 300
#define IOU_THR 0.7f
#define REG_OFF (M_ROWS*NANC)            /* 147456 */
#define PROP_OFF (REG_OFF + M_ROWS*NANC*4) /* 737280 */

// ---------------- scratch (device globals; no allocation) ----------------
__device__ float g_h[M_ROWS*N1];            // bottleneck activations (32MB)
__device__ float g_boxes[NBOX*4];           // decoded+clipped boxes
__device__ unsigned long long g_keys[NBOX]; // (score_bits<<32)|~idx
__device__ float g_cboxes[PRE_NMS*4];
__device__ unsigned long long g_ckeys[PRE_NMS];
__device__ unsigned int g_hist[256];
__device__ unsigned long long g_prefix;
__device__ int g_krem;
__device__ int g_count;

// ---------------- kernel 1: bottleneck GEMM + bias + relu ----------------
// C[16384,512] = relu(A[16384,1024] @ W[1024,512] + b)
// 128x128 block tile, BK=8, 256 threads, 8x8 per thread.
__global__ __launch_bounds__(256, 2)
void gemm_bneck(const float* __restrict__ A, const float* __restrict__ W,
                const float* __restrict__ bias) {
    __shared__ float As[8][128];
    __shared__ float Bs[8][128];
    const int bx = blockIdx.x;            // 0..3  (N tiles)
    const int by = blockIdx.y;            // 0..127 (M tiles)
    const int tid = threadIdx.x;
    const int tx = tid & 15;
    const int ty = tid >> 4;
    const int m0 = by * 128, n0 = bx * 128;

    const int arow = tid >> 1;            // 0..127
    const int acol = (tid & 1) * 4;       // 0 or 4
    const int brow = tid >> 5;            // 0..7
    const int bcol = (tid & 31) * 4;

    const float* Aptr = A + (size_t)(m0 + arow) * K1 + acol;
    const float* Wptr = W + (size_t)brow * N1 + n0 + bcol;

    float acc[8][8];
#pragma unroll
    for (int i = 0; i < 8; i++)
#pragma unroll
        for (int j = 0; j < 8; j++) acc[i][j] = 0.f;

    for (int k0 = 0; k0 < K1; k0 += 8) {
        float4 a = *(const float4*)(Aptr + k0);
        float4 b = *(const float4*)(Wptr + (size_t)k0 * N1);
        As[acol + 0][arow] = a.x;
        As[acol + 1][arow] = a.y;
        As[acol + 2][arow] = a.z;
        As[acol + 3][arow] = a.w;
        *(float4*)&Bs[brow][bcol] = b;
        __syncthreads();
#pragma unroll
        for (int k = 0; k < 8; k++) {
            float ra[8], rb[8];
            *(float4*)&ra[0] = *(const float4*)&As[k][ty * 8];
            *(float4*)&ra[4] = *(const float4*)&As[k][ty * 8 + 4];
            *(float4*)&rb[0] = *(const float4*)&Bs[k][tx * 8];
            *(float4*)&rb[4] = *(const float4*)&Bs[k][tx * 8 + 4];
#pragma unroll
            for (int i = 0; i < 8; i++)
#pragma unroll
                for (int j = 0; j < 8; j++) acc[i][j] += ra[i] * rb[j];
        }
        __syncthreads();
    }
    float bb[8];
    *(float4*)&bb[0] = *(const float4*)&bias[n0 + tx * 8];
    *(float4*)&bb[4] = *(const float4*)&bias[n0 + tx * 8 + 4];
#pragma unroll
    for (int i = 0; i < 8; i++) {
        const int m = m0 + ty * 8 + i;
        float4 o0, o1;
        o0.x = fmaxf(acc[i][0] + bb[0], 0.f);
        o0.y = fmaxf(acc[i][1] + bb[1], 0.f);
        o0.z = fmaxf(acc[i][2] + bb[2], 0.f);
        o0.w = fmaxf(acc[i][3] + bb[3], 0.f);
        o1.x = fmaxf(acc[i][4] + bb[4], 0.f);
        o1.y = fmaxf(acc[i][5] + bb[5], 0.f);
        o1.z = fmaxf(acc[i][6] + bb[6], 0.f);
        o1.w = fmaxf(acc[i][7] + bb[7], 0.f);
        *(float4*)&g_h[(size_t)m * N1 + n0 + tx * 8]     = o0;
        *(float4*)&g_h[(size_t)m * N1 + n0 + tx * 8 + 4] = o1;
    }
}

// ---------------- kernel 2: head GEMM + sigmoid + box decode ----------------
// out45[64 rows, 45 cols] per block; K=512, BK=32, 256 threads, 4x3 per thread.
__global__ __launch_bounds__(256, 4)
void head_kernel(const float* __restrict__ ancs,
                 const float* __restrict__ wc, const float* __restrict__ bc,
                 const float* __restrict__ wr, const float* __restrict__ br,
                 float* __restrict__ out) {
    __shared__ float Hs[32][64];
    __shared__ float Ws[32][48];
    __shared__ float Os[64][48];
    const int tid = threadIdx.x;
    const int tx = tid & 15;      // col group
    const int ty = tid >> 4;      // row group
    const int gr0 = blockIdx.x * 64;

    float acc[4][3];
#pragma unroll
    for (int i = 0; i < 4; i++)
#pragma unroll
        for (int j = 0; j < 3; j++) acc[i][j] = 0.f;

    for (int k0 = 0; k0 < N1; k0 += 32) {
        // load H tile [64 rows x 32 k] transposed into Hs[k][m]
#pragma unroll
        for (int v = 0; v < 2; v++) {
            int lin = tid * 8 + v * 4;
            int r = lin >> 5;
            int c = lin & 31;
            float4 h4 = *(const float4*)&g_h[(size_t)(gr0 + r) * N1 + k0 + c];
            Hs[c + 0][r] = h4.x; Hs[c + 1][r] = h4.y;
            Hs[c + 2][r] = h4.z; Hs[c + 3][r] = h4.w;
        }
        // load W tile [32 k x 48 cols]
        for (int idx = tid; idx < 32 * 48; idx += 256) {
            int r = idx / 48, o = idx % 48;
            float v = 0.f;
            if (o < 9)       v = wc[(size_t)(k0 + r) * 9 + o];
            else if (o < 45) v = wr[(size_t)(k0 + r) * 36 + (o - 9)];
            Ws[r][o] = v;
        }
        __syncthreads();
#pragma unroll
        for (int k = 0; k < 32; k++) {
            float a0 = Hs[k][ty * 4 + 0], a1 = Hs[k][ty * 4 + 1];
            float a2 = Hs[k][ty * 4 + 2], a3 = Hs[k][ty * 4 + 3];
            float b0 = Ws[k][tx * 3 + 0], b1 = Ws[k][tx * 3 + 1], b2 = Ws[k][tx * 3 + 2];
            acc[0][0] += a0 * b0; acc[0][1] += a0 * b1; acc[0][2] += a0 * b2;
            acc[1][0] += a1 * b0; acc[1][1] += a1 * b1; acc[1][2] += a1 * b2;
            acc[2][0] += a2 * b0; acc[2][1] += a2 * b1; acc[2][2] += a2 * b2;
            acc[3][0] += a3 * b0; acc[3][1] += a3 * b1; acc[3][2] += a3 * b2;
        }
        __syncthreads();
    }
    // bias + stash in shared
#pragma unroll
    for (int i = 0; i < 4; i++)
#pragma unroll
        for (int j = 0; j < 3; j++) {
            int o = tx * 3 + j;
            float bia = (o < 9) ? bc[o] : ((o < 45) ? br[o - 9] : 0.f);
            Os[ty * 4 + i][o] = acc[i][j] + bia;
        }
    __syncthreads();
    // write cls (sigmoid) and reg
    for (int idx = tid; idx < 64 * 45; idx += 256) {
        int r = idx / 45, o = idx % 45;
        float v = Os[r][o];
        int grow = gr0 + r;
        if (o < 9) out[(size_t)grow * 9 + o] = 1.f / (1.f + expf(-v));
        else       out[REG_OFF + (size_t)grow * 36 + (o - 9)] = v;
    }
    // decode boxes + build keys
    for (int t = tid; t < 64 * 9; t += 256) {
        int r = t / 9, a = t % 9;
        int gi = (gr0 + r) * 9 + a;
        float logit = Os[r][a];
        float score = 1.f / (1.f + expf(-logit));
        float tx_ = Os[r][9 + a * 4 + 0];
        float ty_ = Os[r][9 + a * 4 + 1];
        float tw_ = Os[r][9 + a * 4 + 2];
        float th_ = Os[r][9 + a * 4 + 3];
        float acx = ancs[(size_t)gi * 4 + 0];
        float acy = ancs[(size_t)gi * 4 + 1];
        float aw  = ancs[(size_t)gi * 4 + 2];
        float ah  = ancs[(size_t)gi * 4 + 3];
        float cx = acx + tx_ * aw;
        float cy = acy + ty_ * ah;
        float ww = aw * expf(tw_);
        float hh = ah * expf(th_);
        float x1 = fminf(fmaxf(cx - ww * 0.5f, 0.f), 1.f);
        float y1 = fminf(fmaxf(cy - hh * 0.5f, 0.f), 1.f);
        float x2 = fminf(fmaxf(cx + ww * 0.5f, 0.f), 1.f);
        float y2 = fminf(fmaxf(cy + hh * 0.5f, 0.f), 1.f);
        g_boxes[(size_t)gi * 4 + 0] = x1;
        g_boxes[(size_t)gi * 4 + 1] = y1;
        g_boxes[(size_t)gi * 4 + 2] = x2;
        g_boxes[(size_t)gi * 4 + 3] = y2;
        unsigned sb = __float_as_uint(score);     // score>0 -> monotone bits
        g_keys[gi] = ((unsigned long long)sb << 32) | (unsigned long long)(~(unsigned)gi);
    }
}

// ---------------- selection: exact 64-bit radix select (top-6000) ----------------
__global__ void sel_init() {
    int t = threadIdx.x;
    g_hist[t] = 0u;
    if (t == 0) { g_prefix = 0ull; g_krem = PRE_NMS; g_count = 0; }
}

__global__ void hist_pass(int shift) {
    __shared__ unsigned int sh[256];
    sh[threadIdx.x] = 0u;
    __syncthreads();
    unsigned long long pref = g_prefix;
    unsigned long long mask = (shift == 56) ? 0ull : (~0ull << (shift + 8));
    for (int i = blockIdx.x * blockDim.x + threadIdx.x; i < NBOX; i += gridDim.x * blockDim.x) {
        unsigned long long k = g_keys[i];
        if (((k ^ pref) & mask) == 0ull)
            atomicAdd(&sh[(unsigned)(k >> shift) & 255u], 1u);
    }
    __syncthreads();
    if (sh[threadIdx.x]) atomicAdd(&g_hist[threadIdx.x], sh[threadIdx.x]);
}

__global__ void scan_pass(int shift) {
    int k = g_krem;
    int b = 255;
    for (; b >= 0; --b) {
        int c = (int)g_hist[b];
        if (c >= k) break;
        k -= c;
    }
    if (b < 0) b = 0;
    g_prefix |= ((unsigned long long)(unsigned)b) << shift;
    g_krem = k;
    for (int i = 0; i < 256; i++) g_hist[i] = 0u;
}

__global__ void compact_kernel() {
    unsigned long long thr = g_prefix;   // exact 6000th-largest key
    for (int i = blockIdx.x * blockDim.x + threadIdx.x; i < NBOX; i += gridDim.x * blockDim.x) {
        unsigned long long k = g_keys[i];
        if (k >= thr) {
            int pos = atomicAdd(&g_count, 1);
            if (pos < PRE_NMS) {
                g_ckeys[pos] = k;
                g_cboxes[(size_t)pos * 4 + 0] = g_boxes[(size_t)i * 4 + 0];
                g_cboxes[(size_t)pos * 4 + 1] = g_boxes[(size_t)i * 4 + 1];
                g_cboxes[(size_t)pos * 4 + 2] = g_boxes[(size_t)i * 4 + 2];
                g_cboxes[(size_t)pos * 4 + 3] = g_boxes[(size_t)i * 4 + 3];
            }
        }
    }
}

// ---------------- NMS: single block, boxes resident in SMEM ----------------
__global__ __launch_bounds__(1024)
void nms_kernel(float* __restrict__ out) {
    extern __shared__ unsigned char smem[];
    unsigned long long* s_key = (unsigned long long*)smem;          // 48000B
    float* s_x1 = (float*)(smem + 48000);
    float* s_y1 = (float*)(smem + 48000 + 24000);
    float* s_x2 = (float*)(smem + 48000 + 48000);
    float* s_y2 = (float*)(smem + 48000 + 72000);
    float* s_ar = (float*)(smem + 48000 + 96000);

    __shared__ unsigned long long s_rk[32];
    __shared__ int s_ri[32];
    __shared__ int s_widx;
    __shared__ unsigned long long s_wkey;

    const int tid = threadIdx.x;
    const int lane = tid & 31;
    const int wid = tid >> 5;
    const int nvalid = min(g_count, PRE_NMS);

    for (int i = tid; i < PRE_NMS; i += 1024) {
        if (i < nvalid) {
            s_key[i] = g_ckeys[i];
            float x1 = g_cboxes[(size_t)i * 4 + 0];
            float y1 = g_cboxes[(size_t)i * 4 + 1];
            float x2 = g_cboxes[(size_t)i * 4 + 2];
            float y2 = g_cboxes[(size_t)i * 4 + 3];
            s_x1[i] = x1; s_y1[i] = y1; s_x2[i] = x2; s_y2[i] = y2;
            s_ar[i] = (x2 - x1) * (y2 - y1);
        } else {
            s_key[i] = 0ull;
            s_x1[i] = 0.f; s_y1[i] = 0.f; s_x2[i] = 0.f; s_y2[i] = 0.f; s_ar[i] = 0.f;
        }
    }
    __syncthreads();

    for (int it = 0; it < POST_NMS; it++) {
        // block argmax over keys
        unsigned long long bk = 0ull; int bi = -1;
        for (int i = tid; i < PRE_NMS; i += 1024) {
            unsigned long long k = s_key[i];
            if (k > bk) { bk = k; bi = i; }
        }
#pragma unroll
        for (int off = 16; off > 0; off >>= 1) {
            unsigned long long ok = __shfl_down_sync(0xffffffffu, bk, off);
            int oi = __shfl_down_sync(0xffffffffu, bi, off);
            if (ok > bk) { bk = ok; bi = oi; }
        }
        if (lane == 0) { s_rk[wid] = bk; s_ri[wid] = bi; }
        __syncthreads();
        if (wid == 0) {
            bk = s_rk[lane]; bi = s_ri[lane];
#pragma unroll
            for (int off = 16; off > 0; off >>= 1) {
                unsigned long long ok = __shfl_down_sync(0xffffffffu, bk, off);
                int oi = __shfl_down_sync(0xffffffffu, bi, off);
                if (ok > bk) { bk = ok; bi = oi; }
            }
            if (lane == 0) { s_widx = bi; s_wkey = bk; }
        }
        __syncthreads();

        if (s_wkey == 0ull) {
            if (tid == 0) {
                out[PROP_OFF + it * 4 + 0] = 0.f;
                out[PROP_OFF + it * 4 + 1] = 0.f;
                out[PROP_OFF + it * 4 + 2] = 0.f;
                out[PROP_OFF + it * 4 + 3] = 0.f;
            }
            __syncthreads();
            continue;
        }
        const int w = s_widx;
        const float wx1 = s_x1[w], wy1 = s_y1[w], wx2 = s_x2[w], wy2 = s_y2[w];
        const float wa = s_ar[w];
        if (tid == 0) {
            out[PROP_OFF + it * 4 + 0] = wx1;
            out[PROP_OFF + it * 4 + 1] = wy1;
            out[PROP_OFF + it * 4 + 2] = wx2;
            out[PROP_OFF + it * 4 + 3] = wy2;
            s_key[w] = 0ull;
        }
        for (int i = tid; i < PRE_NMS; i += 1024) {
            unsigned long long k = s_key[i];
            if (k != 0ull) {
                float iw = fminf(wx2, s_x2[i]) - fmaxf(wx1, s_x1[i]);
                float ih = fminf(wy2, s_y2[i]) - fmaxf(wy1, s_y1[i]);
                iw = fmaxf(iw, 0.f);
                ih = fmaxf(ih, 0.f);
                float inter = iw * ih;
                float uni = wa + s_ar[i] - inter;
                float iou = (uni > 0.f) ? inter / uni : 0.f;
                if (iou > IOU_THR) s_key[i] = 0ull;
            }
        }
        __syncthreads();
    }
}

// ---------------- launcher ----------------
extern "C" void kernel_launch(void* const* d_in, const int* in_sizes, int n_in,
                              void* d_out, int out_size) {
    const float* feats   = (const float*)d_in[0];
    const float* ancs    = (const float*)d_in[1];
    /* ancs_valid d_in[2] unused by reference */
    const float* w_bneck = (const float*)d_in[3];
    const float* b_bneck = (const float*)d_in[4];
    const float* w_cls   = (const float*)d_in[5];
    const float* b_cls   = (const float*)d_in[6];
    const float* w_reg   = (const float*)d_in[7];
    const float* b_reg   = (const float*)d_in[8];
    float* out = (float*)d_out;

    cudaFuncSetAttribute(nms_kernel, cudaFuncAttributeMaxDynamicSharedMemorySize, 168000);

    gemm_bneck<<<dim3(4, 128), 256>>>(feats, w_bneck, b_bneck);
    head_kernel<<<M_ROWS / 64, 256>>>(ancs, w_cls, b_cls, w_reg, b_reg, out);
    sel_init<<<1, 256>>>();
    for (int p = 7; p >= 0; --p) {
        hist_pass<<<288, 256>>>(p * 8);
        scan_pass<<<1, 1>>>(p * 8);
    }
    compact_kernel<<<288, 256>>>();
    nms_kernel<<<1, 1024, 168000>>>(out);
}

// round 4
// speedup vs baseline: 1.1103x; 1.1101x over previous
#include <cuda_runtime.h>
#include <math.h>
#include <stdint.h>

#define M_ROWS 16384
#define K1 1024
#define N1 512
#define NANC 9
#define NBOX (M_ROWS*NANC)          /* 147456 */
#define PRE_NMS 6000
#define POST_NMS 300
#define IOU_THR 0.7f
#define REG_OFF (M_ROWS*NANC)            /* 147456 */
#define PROP_OFF (REG_OFF + M_ROWS*NANC*4) /* 737280 */

// ---------------- scratch (device globals; no allocation) ----------------
__device__ float g_h[M_ROWS*N1];            // bottleneck activations (32MB)
__device__ float g_boxes[NBOX*4];           // decoded+clipped boxes
__device__ unsigned long long g_keys[NBOX]; // (score_bits<<32)|~idx
__device__ float g_cboxes[PRE_NMS*4];
__device__ unsigned long long g_ckeys[PRE_NMS];
__device__ unsigned int g_hist[256];
__device__ unsigned long long g_prefix;
__device__ int g_krem;
__device__ int g_count;

// ================= helpers =================
__device__ __forceinline__ uint32_t smem_u32(const void* p) {
    uint32_t a;
    asm("{ .reg .u64 t; cvta.to.shared.u64 t, %1; cvt.u32.u64 %0, t; }" : "=r"(a) : "l"(p));
    return a;
}
__device__ __forceinline__ uint32_t tf32_hi(float x) {
    uint32_t r;
    asm("cvt.rna.tf32.f32 %0, %1;" : "=r"(r) : "f"(x));
    return r;
}
__device__ __forceinline__ void split_tf32(float x, uint32_t& hi, uint32_t& lo) {
    hi = tf32_hi(x);
    lo = tf32_hi(x - __uint_as_float(hi));
}
__device__ __forceinline__ void mma_tf32(float* c, const uint32_t* a, uint32_t b0, uint32_t b1) {
    asm volatile(
        "mma.sync.aligned.m16n8k8.row.col.f32.tf32.tf32.f32 "
        "{%0,%1,%2,%3}, {%4,%5,%6,%7}, {%8,%9}, {%0,%1,%2,%3};"
        : "+f"(c[0]), "+f"(c[1]), "+f"(c[2]), "+f"(c[3])
        : "r"(a[0]), "r"(a[1]), "r"(a[2]), "r"(a[3]), "r"(b0), "r"(b1));
}
__device__ __forceinline__ void cp_async16(uint32_t dst, const void* src) {
    asm volatile("cp.async.ca.shared.global [%0], [%1], 16;" :: "r"(dst), "l"(src) : "memory");
}

// ================= kernel 1: split-TF32 warp-MMA bottleneck GEMM =================
// C[16384,512] = relu(A[16384,1024] @ W[1024,512] + b)
// CTA: 128(M) x 128(N), 256 threads (8 warps of 32x64), K-chunk 32, 2-stage cp.async.
// Raw fp32 in SMEM; hi/lo tf32 split at fragment-load time.
// D += Ah*Bh + Ah*Bl + Al*Bh  (3xTF32 ~ fp32 accuracy, err ~2^-22)

#define PADA 36   /* floats per A row in smem */
#define PADB 136  /* floats per B row in smem (136%32==8 -> conflict-free frags) */
#define A_BUF_BYTES (128*PADA*4)   /* 18432 */
#define B_BUF_BYTES (32*PADB*4)    /* 17408 */
#define GEMM_SMEM (2*A_BUF_BYTES + 2*B_BUF_BYTES) /* 71680 */

__global__ __launch_bounds__(256, 2)
void gemm_bneck_mma(const float* __restrict__ A, const float* __restrict__ W,
                    const float* __restrict__ bias) {
    extern __shared__ float sm[];
    float* As = sm;                          // [2][128][PADA]
    float* Bs = sm + 2*128*PADA;             // [2][32][PADB]
    const uint32_t sA = smem_u32(As);
    const uint32_t sB = smem_u32(Bs);

    const int tid = threadIdx.x;
    const int lane = tid & 31;
    const int wid = tid >> 5;
    const int m0 = blockIdx.y * 128;
    const int n0 = blockIdx.x * 128;
    const int mrow = (wid & 3) * 32;         // warp M offset within CTA tile
    const int ncol = (wid >> 2) * 64;        // warp N offset within CTA tile
    const int quad = lane >> 2;              // 0..7
    const int tq = lane & 3;                 // 0..3

    float c[2][8][4];
#pragma unroll
    for (int mt = 0; mt < 2; mt++)
#pragma unroll
        for (int nt = 0; nt < 8; nt++)
#pragma unroll
            for (int j = 0; j < 4; j++) c[mt][nt][j] = 0.f;

    // ---- prefetch helper (stage s into buffer buf) ----
    auto prefetch = [&](int s, int buf) {
        const int k0 = s * 32;
#pragma unroll
        for (int i = 0; i < 4; i++) {          // A: 128x32 floats = 1024 f4
            int idx = tid + i * 256;
            int r = idx >> 3, c4 = idx & 7;
            cp_async16(sA + (uint32_t)buf * A_BUF_BYTES + (uint32_t)(r * PADA + c4 * 4) * 4,
                       A + (size_t)(m0 + r) * K1 + k0 + c4 * 4);
        }
#pragma unroll
        for (int i = 0; i < 4; i++) {          // B: 32x128 floats = 1024 f4
            int idx = tid + i * 256;
            int r = idx >> 5, c4 = idx & 31;
            cp_async16(sB + (uint32_t)buf * B_BUF_BYTES + (uint32_t)(r * PADB + c4 * 4) * 4,
                       W + (size_t)(k0 + r) * N1 + n0 + c4 * 4);
        }
        asm volatile("cp.async.commit_group;" ::: "memory");
    };

    prefetch(0, 0);

    for (int s = 0; s < 32; s++) {
        const int buf = s & 1;
        if (s < 31) {
            prefetch(s + 1, buf ^ 1);
            asm volatile("cp.async.wait_group 1;" ::: "memory");
        } else {
            asm volatile("cp.async.wait_group 0;" ::: "memory");
        }
        __syncthreads();

        const float* Ab = As + buf * (128 * PADA);
        const float* Bb = Bs + buf * (32 * PADB);

#pragma unroll
        for (int kk = 0; kk < 4; kk++) {
            // A fragments (2 m-tiles), split into hi/lo
            uint32_t ah[2][4], al[2][4];
#pragma unroll
            for (int mt = 0; mt < 2; mt++) {
                const int rbase = mrow + mt * 16 + quad;
                const int cbase = kk * 8 + tq;
                float r0 = Ab[(rbase)     * PADA + cbase];
                float r1 = Ab[(rbase + 8) * PADA + cbase];
                float r2 = Ab[(rbase)     * PADA + cbase + 4];
                float r3 = Ab[(rbase + 8) * PADA + cbase + 4];
                split_tf32(r0, ah[mt][0], al[mt][0]);
                split_tf32(r1, ah[mt][1], al[mt][1]);
                split_tf32(r2, ah[mt][2], al[mt][2]);
                split_tf32(r3, ah[mt][3], al[mt][3]);
            }
#pragma unroll
            for (int nt = 0; nt < 8; nt++) {
                const int n = ncol + nt * 8 + quad;
                float b0r = Bb[(kk * 8 + tq)     * PADB + n];
                float b1r = Bb[(kk * 8 + tq + 4) * PADB + n];
                uint32_t bh0, bl0, bh1, bl1;
                split_tf32(b0r, bh0, bl0);
                split_tf32(b1r, bh1, bl1);
#pragma unroll
                for (int mt = 0; mt < 2; mt++) {
                    mma_tf32(c[mt][nt], ah[mt], bh0, bh1);
                    mma_tf32(c[mt][nt], ah[mt], bl0, bl1);
                    mma_tf32(c[mt][nt], al[mt], bh0, bh1);
                }
            }
        }
        __syncthreads();
    }

    // ---- epilogue: bias + relu + store ----
#pragma unroll
    for (int nt = 0; nt < 8; nt++) {
        const int nc = n0 + ncol + nt * 8 + 2 * tq;
        const float bia0 = __ldg(&bias[nc]);
        const float bia1 = __ldg(&bias[nc + 1]);
#pragma unroll
        for (int mt = 0; mt < 2; mt++) {
            const int row0 = m0 + mrow + mt * 16 + quad;
            float2 v01, v23;
            v01.x = fmaxf(c[mt][nt][0] + bia0, 0.f);
            v01.y = fmaxf(c[mt][nt][1] + bia1, 0.f);
            v23.x = fmaxf(c[mt][nt][2] + bia0, 0.f);
            v23.y = fmaxf(c[mt][nt][3] + bia1, 0.f);
            *(float2*)&g_h[(size_t)row0 * N1 + nc]       = v01;
            *(float2*)&g_h[(size_t)(row0 + 8) * N1 + nc] = v23;
        }
    }
}

// ---------------- kernel 2: head GEMM + sigmoid + box decode ----------------
__global__ __launch_bounds__(256, 4)
void head_kernel(const float* __restrict__ ancs,
                 const float* __restrict__ wc, const float* __restrict__ bc,
                 const float* __restrict__ wr, const float* __restrict__ br,
                 float* __restrict__ out) {
    __shared__ float Hs[32][64];
    __shared__ float Ws[32][48];
    __shared__ float Os[64][48];
    const int tid = threadIdx.x;
    const int tx = tid & 15;
    const int ty = tid >> 4;
    const int gr0 = blockIdx.x * 64;

    float acc[4][3];
#pragma unroll
    for (int i = 0; i < 4; i++)
#pragma unroll
        for (int j = 0; j < 3; j++) acc[i][j] = 0.f;

    for (int k0 = 0; k0 < N1; k0 += 32) {
#pragma unroll
        for (int v = 0; v < 2; v++) {
            int lin = tid * 8 + v * 4;
            int r = lin >> 5;
            int c = lin & 31;
            float4 h4 = *(const float4*)&g_h[(size_t)(gr0 + r) * N1 + k0 + c];
            Hs[c + 0][r] = h4.x; Hs[c + 1][r] = h4.y;
            Hs[c + 2][r] = h4.z; Hs[c + 3][r] = h4.w;
        }
        for (int idx = tid; idx < 32 * 48; idx += 256) {
            int r = idx / 48, o = idx % 48;
            float v = 0.f;
            if (o < 9)       v = wc[(size_t)(k0 + r) * 9 + o];
            else if (o < 45) v = wr[(size_t)(k0 + r) * 36 + (o - 9)];
            Ws[r][o] = v;
        }
        __syncthreads();
#pragma unroll
        for (int k = 0; k < 32; k++) {
            float a0 = Hs[k][ty * 4 + 0], a1 = Hs[k][ty * 4 + 1];
            float a2 = Hs[k][ty * 4 + 2], a3 = Hs[k][ty * 4 + 3];
            float b0 = Ws[k][tx * 3 + 0], b1 = Ws[k][tx * 3 + 1], b2 = Ws[k][tx * 3 + 2];
            acc[0][0] += a0 * b0; acc[0][1] += a0 * b1; acc[0][2] += a0 * b2;
            acc[1][0] += a1 * b0; acc[1][1] += a1 * b1; acc[1][2] += a1 * b2;
            acc[2][0] += a2 * b0; acc[2][1] += a2 * b1; acc[2][2] += a2 * b2;
            acc[3][0] += a3 * b0; acc[3][1] += a3 * b1; acc[3][2] += a3 * b2;
        }
        __syncthreads();
    }
#pragma unroll
    for (int i = 0; i < 4; i++)
#pragma unroll
        for (int j = 0; j < 3; j++) {
            int o = tx * 3 + j;
            float bia = (o < 9) ? bc[o] : ((o < 45) ? br[o - 9] : 0.f);
            Os[ty * 4 + i][o] = acc[i][j] + bia;
        }
    __syncthreads();
    for (int idx = tid; idx < 64 * 45; idx += 256) {
        int r = idx / 45, o = idx % 45;
        float v = Os[r][o];
        int grow = gr0 + r;
        if (o < 9) out[(size_t)grow * 9 + o] = 1.f / (1.f + expf(-v));
        else       out[REG_OFF + (size_t)grow * 36 + (o - 9)] = v;
    }
    for (int t = tid; t < 64 * 9; t += 256) {
        int r = t / 9, a = t % 9;
        int gi = (gr0 + r) * 9 + a;
        float logit = Os[r][a];
        float score = 1.f / (1.f + expf(-logit));
        float tx_ = Os[r][9 + a * 4 + 0];
        float ty_ = Os[r][9 + a * 4 + 1];
        float tw_ = Os[r][9 + a * 4 + 2];
        float th_ = Os[r][9 + a * 4 + 3];
        float acx = ancs[(size_t)gi * 4 + 0];
        float acy = ancs[(size_t)gi * 4 + 1];
        float aw  = ancs[(size_t)gi * 4 + 2];
        float ah  = ancs[(size_t)gi * 4 + 3];
        float cx = acx + tx_ * aw;
        float cy = acy + ty_ * ah;
        float ww = aw * expf(tw_);
        float hh = ah * expf(th_);
        float x1 = fminf(fmaxf(cx - ww * 0.5f, 0.f), 1.f);
        float y1 = fminf(fmaxf(cy - hh * 0.5f, 0.f), 1.f);
        float x2 = fminf(fmaxf(cx + ww * 0.5f, 0.f), 1.f);
        float y2 = fminf(fmaxf(cy + hh * 0.5f, 0.f), 1.f);
        g_boxes[(size_t)gi * 4 + 0] = x1;
        g_boxes[(size_t)gi * 4 + 1] = y1;
        g_boxes[(size_t)gi * 4 + 2] = x2;
        g_boxes[(size_t)gi * 4 + 3] = y2;
        unsigned sb = __float_as_uint(score);
        g_keys[gi] = ((unsigned long long)sb << 32) | (unsigned long long)(~(unsigned)gi);
    }
}

// ---------------- selection: exact 64-bit radix select (top-6000) ----------------
__global__ void sel_init() {
    int t = threadIdx.x;
    g_hist[t] = 0u;
    if (t == 0) { g_prefix = 0ull; g_krem = PRE_NMS; g_count = 0; }
}

__global__ void hist_pass(int shift) {
    __shared__ unsigned int sh[256];
    sh[threadIdx.x] = 0u;
    __syncthreads();
    unsigned long long pref = g_prefix;
    unsigned long long mask = (shift == 56) ? 0ull : (~0ull << (shift + 8));
    for (int i = blockIdx.x * blockDim.x + threadIdx.x; i < NBOX; i += gridDim.x * blockDim.x) {
        unsigned long long k = g_keys[i];
        if (((k ^ pref) & mask) == 0ull)
            atomicAdd(&sh[(unsigned)(k >> shift) & 255u], 1u);
    }
    __syncthreads();
    if (sh[threadIdx.x]) atomicAdd(&g_hist[threadIdx.x], sh[threadIdx.x]);
}

__global__ void scan_pass(int shift) {
    int k = g_krem;
    int b = 255;
    for (; b >= 0; --b) {
        int c = (int)g_hist[b];
        if (c >= k) break;
        k -= c;
    }
    if (b < 0) b = 0;
    g_prefix |= ((unsigned long long)(unsigned)b) << shift;
    g_krem = k;
    for (int i = 0; i < 256; i++) g_hist[i] = 0u;
}

__global__ void compact_kernel() {
    unsigned long long thr = g_prefix;
    for (int i = blockIdx.x * blockDim.x + threadIdx.x; i < NBOX; i += gridDim.x * blockDim.x) {
        unsigned long long k = g_keys[i];
        if (k >= thr) {
            int pos = atomicAdd(&g_count, 1);
            if (pos < PRE_NMS) {
                g_ckeys[pos] = k;
                g_cboxes[(size_t)pos * 4 + 0] = g_boxes[(size_t)i * 4 + 0];
                g_cboxes[(size_t)pos * 4 + 1] = g_boxes[(size_t)i * 4 + 1];
                g_cboxes[(size_t)pos * 4 + 2] = g_boxes[(size_t)i * 4 + 2];
                g_cboxes[(size_t)pos * 4 + 3] = g_boxes[(size_t)i * 4 + 3];
            }
        }
    }
}

// ---------------- NMS: single block, boxes resident in SMEM ----------------
__global__ __launch_bounds__(1024)
void nms_kernel(float* __restrict__ out) {
    extern __shared__ unsigned char smem[];
    unsigned long long* s_key = (unsigned long long*)smem;
    float* s_x1 = (float*)(smem + 48000);
    float* s_y1 = (float*)(smem + 48000 + 24000);
    float* s_x2 = (float*)(smem + 48000 + 48000);
    float* s_y2 = (float*)(smem + 48000 + 72000);
    float* s_ar = (float*)(smem + 48000 + 96000);

    __shared__ unsigned long long s_rk[32];
    __shared__ int s_ri[32];
    __shared__ int s_widx;
    __shared__ unsigned long long s_wkey;

    const int tid = threadIdx.x;
    const int lane = tid & 31;
    const int wid = tid >> 5;
    const int nvalid = min(g_count, PRE_NMS);

    for (int i = tid; i < PRE_NMS; i += 1024) {
        if (i < nvalid) {
            s_key[i] = g_ckeys[i];
            float x1 = g_cboxes[(size_t)i * 4 + 0];
            float y1 = g_cboxes[(size_t)i * 4 + 1];
            float x2 = g_cboxes[(size_t)i * 4 + 2];
            float y2 = g_cboxes[(size_t)i * 4 + 3];
            s_x1[i] = x1; s_y1[i] = y1; s_x2[i] = x2; s_y2[i] = y2;
            s_ar[i] = (x2 - x1) * (y2 - y1);
        } else {
            s_key[i] = 0ull;
            s_x1[i] = 0.f; s_y1[i] = 0.f; s_x2[i] = 0.f; s_y2[i] = 0.f; s_ar[i] = 0.f;
        }
    }
    __syncthreads();

    for (int it = 0; it < POST_NMS; it++) {
        unsigned long long bk = 0ull; int bi = -1;
        for (int i = tid; i < PRE_NMS; i += 1024) {
            unsigned long long k = s_key[i];
            if (k > bk) { bk = k; bi = i; }
        }
#pragma unroll
        for (int off = 16; off > 0; off >>= 1) {
            unsigned long long ok = __shfl_down_sync(0xffffffffu, bk, off);
            int oi = __shfl_down_sync(0xffffffffu, bi, off);
            if (ok > bk) { bk = ok; bi = oi; }
        }
        if (lane == 0) { s_rk[wid] = bk; s_ri[wid] = bi; }
        __syncthreads();
        if (wid == 0) {
            bk = s_rk[lane]; bi = s_ri[lane];
#pragma unroll
            for (int off = 16; off > 0; off >>= 1) {
                unsigned long long ok = __shfl_down_sync(0xffffffffu, bk, off);
                int oi = __shfl_down_sync(0xffffffffu, bi, off);
                if (ok > bk) { bk = ok; bi = oi; }
            }
            if (lane == 0) { s_widx = bi; s_wkey = bk; }
        }
        __syncthreads();

        if (s_wkey == 0ull) {
            if (tid == 0) {
                out[PROP_OFF + it * 4 + 0] = 0.f;
                out[PROP_OFF + it * 4 + 1] = 0.f;
                out[PROP_OFF + it * 4 + 2] = 0.f;
                out[PROP_OFF + it * 4 + 3] = 0.f;
            }
            __syncthreads();
            continue;
        }
        const int w = s_widx;
        const float wx1 = s_x1[w], wy1 = s_y1[w], wx2 = s_x2[w], wy2 = s_y2[w];
        const float wa = s_ar[w];
        if (tid == 0) {
            out[PROP_OFF + it * 4 + 0] = wx1;
            out[PROP_OFF + it * 4 + 1] = wy1;
            out[PROP_OFF + it * 4 + 2] = wx2;
            out[PROP_OFF + it * 4 + 3] = wy2;
            s_key[w] = 0ull;
        }
        for (int i = tid; i < PRE_NMS; i += 1024) {
            unsigned long long k = s_key[i];
            if (k != 0ull) {
                float iw = fminf(wx2, s_x2[i]) - fmaxf(wx1, s_x1[i]);
                float ih = fminf(wy2, s_y2[i]) - fmaxf(wy1, s_y1[i]);
                iw = fmaxf(iw, 0.f);
                ih = fmaxf(ih, 0.f);
                float inter = iw * ih;
                float uni = wa + s_ar[i] - inter;
                float iou = (uni > 0.f) ? inter / uni : 0.f;
                if (iou > IOU_THR) s_key[i] = 0ull;
            }
        }
        __syncthreads();
    }
}

// ---------------- launcher ----------------
extern "C" void kernel_launch(void* const* d_in, const int* in_sizes, int n_in,
                              void* d_out, int out_size) {
    const float* feats   = (const float*)d_in[0];
    const float* ancs    = (const float*)d_in[1];
    const float* w_bneck = (const float*)d_in[3];
    const float* b_bneck = (const float*)d_in[4];
    const float* w_cls   = (const float*)d_in[5];
    const float* b_cls   = (const float*)d_in[6];
    const float* w_reg   = (const float*)d_in[7];
    const float* b_reg   = (const float*)d_in[8];
    float* out = (float*)d_out;

    cudaFuncSetAttribute(nms_kernel, cudaFuncAttributeMaxDynamicSharedMemorySize, 168000);
    cudaFuncSetAttribute(gemm_bneck_mma, cudaFuncAttributeMaxDynamicSharedMemorySize, GEMM_SMEM);

    gemm_bneck_mma<<<dim3(4, 128), 256, GEMM_SMEM>>>(feats, w_bneck, b_bneck);
    head_kernel<<<M_ROWS / 64, 256>>>(ancs, w_cls, b_cls, w_reg, b_reg, out);
    sel_init<<<1, 256>>>();
    for (int p = 7; p >= 0; --p) {
        hist_pass<<<288, 256>>>(p * 8);
        scan_pass<<<1, 1>>>(p * 8);
    }
    compact_kernel<<<288, 256>>>();
    nms_kernel<<<1, 1024, 168000>>>(out);
}

// round 5
// speedup vs baseline: 1.6817x; 1.5145x over previous
#include <cuda_runtime.h>
#include <math.h>
#include <stdint.h>

#define M_ROWS 16384
#define K1 1024
#define N1 512
#define NANC 9
#define NBOX (M_ROWS*NANC)          /* 147456 */
#define PRE_NMS 6000
#define POST_NMS 300
#define IOU_THR 0.7f
#define REG_OFF (M_ROWS*NANC)            /* 147456 */
#define PROP_OFF (REG_OFF + M_ROWS*NANC*4) /* 737280 */
#define SEL_BLOCKS 288

// ---------------- scratch (device globals; no allocation) ----------------
__device__ float g_h[M_ROWS*N1];            // bottleneck activations (32MB)
__device__ float g_boxes[NBOX*4];           // decoded+clipped boxes
__device__ unsigned long long g_keys[NBOX]; // (score_bits<<32)|~idx
__device__ float g_cboxes[PRE_NMS*4];
__device__ unsigned long long g_ckeys[PRE_NMS];
__device__ unsigned int g_hist[256];
__device__ unsigned long long g_prefix;
__device__ int g_krem;
__device__ int g_count;
__device__ unsigned int g_bar_count;
__device__ unsigned int g_epoch;

// ================= helpers =================
__device__ __forceinline__ uint32_t smem_u32(const void* p) {
    uint32_t a;
    asm("{ .reg .u64 t; cvta.to.shared.u64 t, %1; cvt.u32.u64 %0, t; }" : "=r"(a) : "l"(p));
    return a;
}
// mask-based tf32 split: hi = a with low 13 mantissa bits zeroed (valid tf32),
// lo = exact residual (representable; HW truncation of lo loses only ~2^-22 rel)
__device__ __forceinline__ void split_tf32(float x, uint32_t& hi, uint32_t& lo) {
    hi = __float_as_uint(x) & 0xFFFFE000u;
    lo = __float_as_uint(x - __uint_as_float(hi));
}
__device__ __forceinline__ void mma_tf32(float* c, const uint32_t* a, uint32_t b0, uint32_t b1) {
    asm volatile(
        "mma.sync.aligned.m16n8k8.row.col.f32.tf32.tf32.f32 "
        "{%0,%1,%2,%3}, {%4,%5,%6,%7}, {%8,%9}, {%0,%1,%2,%3};"
        : "+f"(c[0]), "+f"(c[1]), "+f"(c[2]), "+f"(c[3])
        : "r"(a[0]), "r"(a[1]), "r"(a[2]), "r"(a[3]), "r"(b0), "r"(b1));
}
__device__ __forceinline__ void cp_async16(uint32_t dst, const void* src) {
    asm volatile("cp.async.ca.shared.global [%0], [%1], 16;" :: "r"(dst), "l"(src) : "memory");
}
__device__ __forceinline__ unsigned ld_cg_u32(const unsigned* p) {
    unsigned v;
    asm volatile("ld.global.cg.u32 %0, [%1];" : "=r"(v) : "l"(p) : "memory");
    return v;
}

// ================= kernel 1: split-TF32 warp-MMA bottleneck GEMM =================
#define PADA 36
#define PADB 136
#define A_BUF_BYTES (128*PADA*4)
#define B_BUF_BYTES (32*PADB*4)
#define GEMM_SMEM (2*A_BUF_BYTES + 2*B_BUF_BYTES)

__global__ __launch_bounds__(256, 2)
void gemm_bneck_mma(const float* __restrict__ A, const float* __restrict__ W,
                    const float* __restrict__ bias) {
    extern __shared__ float sm[];
    float* As = sm;
    float* Bs = sm + 2*128*PADA;
    const uint32_t sA = smem_u32(As);
    const uint32_t sB = smem_u32(Bs);

    const int tid = threadIdx.x;
    const int lane = tid & 31;
    const int wid = tid >> 5;
    const int m0 = blockIdx.y * 128;
    const int n0 = blockIdx.x * 128;
    const int mrow = (wid & 3) * 32;
    const int ncol = (wid >> 2) * 64;
    const int quad = lane >> 2;
    const int tq = lane & 3;

    float c[2][8][4];
#pragma unroll
    for (int mt = 0; mt < 2; mt++)
#pragma unroll
        for (int nt = 0; nt < 8; nt++)
#pragma unroll
            for (int j = 0; j < 4; j++) c[mt][nt][j] = 0.f;

    auto prefetch = [&](int s, int buf) {
        const int k0 = s * 32;
#pragma unroll
        for (int i = 0; i < 4; i++) {
            int idx = tid + i * 256;
            int r = idx >> 3, c4 = idx & 7;
            cp_async16(sA + (uint32_t)buf * A_BUF_BYTES + (uint32_t)(r * PADA + c4 * 4) * 4,
                       A + (size_t)(m0 + r) * K1 + k0 + c4 * 4);
        }
#pragma unroll
        for (int i = 0; i < 4; i++) {
            int idx = tid + i * 256;
            int r = idx >> 5, c4 = idx & 31;
            cp_async16(sB + (uint32_t)buf * B_BUF_BYTES + (uint32_t)(r * PADB + c4 * 4) * 4,
                       W + (size_t)(k0 + r) * N1 + n0 + c4 * 4);
        }
        asm volatile("cp.async.commit_group;" ::: "memory");
    };

    prefetch(0, 0);

    for (int s = 0; s < 32; s++) {
        const int buf = s & 1;
        if (s < 31) {
            prefetch(s + 1, buf ^ 1);
            asm volatile("cp.async.wait_group 1;" ::: "memory");
        } else {
            asm volatile("cp.async.wait_group 0;" ::: "memory");
        }
        __syncthreads();

        const float* Ab = As + buf * (128 * PADA);
        const float* Bb = Bs + buf * (32 * PADB);

#pragma unroll
        for (int kk = 0; kk < 4; kk++) {
            uint32_t ah[2][4], al[2][4];
#pragma unroll
            for (int mt = 0; mt < 2; mt++) {
                const int rbase = mrow + mt * 16 + quad;
                const int cbase = kk * 8 + tq;
                float r0 = Ab[(rbase)     * PADA + cbase];
                float r1 = Ab[(rbase + 8) * PADA + cbase];
                float r2 = Ab[(rbase)     * PADA + cbase + 4];
                float r3 = Ab[(rbase + 8) * PADA + cbase + 4];
                split_tf32(r0, ah[mt][0], al[mt][0]);
                split_tf32(r1, ah[mt][1], al[mt][1]);
                split_tf32(r2, ah[mt][2], al[mt][2]);
                split_tf32(r3, ah[mt][3], al[mt][3]);
            }
#pragma unroll
            for (int nt = 0; nt < 8; nt++) {
                const int n = ncol + nt * 8 + quad;
                float b0r = Bb[(kk * 8 + tq)     * PADB + n];
                float b1r = Bb[(kk * 8 + tq + 4) * PADB + n];
                uint32_t bh0, bl0, bh1, bl1;
                split_tf32(b0r, bh0, bl0);
                split_tf32(b1r, bh1, bl1);
#pragma unroll
                for (int mt = 0; mt < 2; mt++) {
                    mma_tf32(c[mt][nt], ah[mt], bh0, bh1);
                    mma_tf32(c[mt][nt], ah[mt], bl0, bl1);
                    mma_tf32(c[mt][nt], al[mt], bh0, bh1);
                }
            }
        }
        __syncthreads();
    }

#pragma unroll
    for (int nt = 0; nt < 8; nt++) {
        const int nc = n0 + ncol + nt * 8 + 2 * tq;
        const float bia0 = __ldg(&bias[nc]);
        const float bia1 = __ldg(&bias[nc + 1]);
#pragma unroll
        for (int mt = 0; mt < 2; mt++) {
            const int row0 = m0 + mrow + mt * 16 + quad;
            float2 v01, v23;
            v01.x = fmaxf(c[mt][nt][0] + bia0, 0.f);
            v01.y = fmaxf(c[mt][nt][1] + bia1, 0.f);
            v23.x = fmaxf(c[mt][nt][2] + bia0, 0.f);
            v23.y = fmaxf(c[mt][nt][3] + bia1, 0.f);
            *(float2*)&g_h[(size_t)row0 * N1 + nc]       = v01;
            *(float2*)&g_h[(size_t)(row0 + 8) * N1 + nc] = v23;
        }
    }
}

// ---------------- kernel 2: head GEMM + sigmoid + box decode ----------------
__global__ __launch_bounds__(256, 4)
void head_kernel(const float* __restrict__ ancs,
                 const float* __restrict__ wc, const float* __restrict__ bc,
                 const float* __restrict__ wr, const float* __restrict__ br,
                 float* __restrict__ out) {
    __shared__ float Hs[32][64];
    __shared__ float Ws[32][48];
    __shared__ float Os[64][48];
    const int tid = threadIdx.x;
    const int tx = tid & 15;
    const int ty = tid >> 4;
    const int gr0 = blockIdx.x * 64;

    // reset selection state for this run (select_all runs strictly after this kernel)
    if (blockIdx.x == 0 && tid == 0) {
        g_prefix = 0ull;
        g_krem = PRE_NMS;
        g_count = 0;
        g_bar_count = 0u;
        g_epoch = 0u;
    }

    float acc[4][3];
#pragma unroll
    for (int i = 0; i < 4; i++)
#pragma unroll
        for (int j = 0; j < 3; j++) acc[i][j] = 0.f;

    for (int k0 = 0; k0 < N1; k0 += 32) {
#pragma unroll
        for (int v = 0; v < 2; v++) {
            int lin = tid * 8 + v * 4;
            int r = lin >> 5;
            int c = lin & 31;
            float4 h4 = *(const float4*)&g_h[(size_t)(gr0 + r) * N1 + k0 + c];
            Hs[c + 0][r] = h4.x; Hs[c + 1][r] = h4.y;
            Hs[c + 2][r] = h4.z; Hs[c + 3][r] = h4.w;
        }
        for (int idx = tid; idx < 32 * 48; idx += 256) {
            int r = idx / 48, o = idx % 48;
            float v = 0.f;
            if (o < 9)       v = wc[(size_t)(k0 + r) * 9 + o];
            else if (o < 45) v = wr[(size_t)(k0 + r) * 36 + (o - 9)];
            Ws[r][o] = v;
        }
        __syncthreads();
#pragma unroll
        for (int k = 0; k < 32; k++) {
            float a0 = Hs[k][ty * 4 + 0], a1 = Hs[k][ty * 4 + 1];
            float a2 = Hs[k][ty * 4 + 2], a3 = Hs[k][ty * 4 + 3];
            float b0 = Ws[k][tx * 3 + 0], b1 = Ws[k][tx * 3 + 1], b2 = Ws[k][tx * 3 + 2];
            acc[0][0] += a0 * b0; acc[0][1] += a0 * b1; acc[0][2] += a0 * b2;
            acc[1][0] += a1 * b0; acc[1][1] += a1 * b1; acc[1][2] += a1 * b2;
            acc[2][0] += a2 * b0; acc[2][1] += a2 * b1; acc[2][2] += a2 * b2;
            acc[3][0] += a3 * b0; acc[3][1] += a3 * b1; acc[3][2] += a3 * b2;
        }
        __syncthreads();
    }
#pragma unroll
    for (int i = 0; i < 4; i++)
#pragma unroll
        for (int j = 0; j < 3; j++) {
            int o = tx * 3 + j;
            float bia = (o < 9) ? bc[o] : ((o < 45) ? br[o - 9] : 0.f);
            Os[ty * 4 + i][o] = acc[i][j] + bia;
        }
    __syncthreads();
    for (int idx = tid; idx < 64 * 45; idx += 256) {
        int r = idx / 45, o = idx % 45;
        float v = Os[r][o];
        int grow = gr0 + r;
        if (o < 9) out[(size_t)grow * 9 + o] = 1.f / (1.f + expf(-v));
        else       out[REG_OFF + (size_t)grow * 36 + (o - 9)] = v;
    }
    for (int t = tid; t < 64 * 9; t += 256) {
        int r = t / 9, a = t % 9;
        int gi = (gr0 + r) * 9 + a;
        float logit = Os[r][a];
        float score = 1.f / (1.f + expf(-logit));
        float tx_ = Os[r][9 + a * 4 + 0];
        float ty_ = Os[r][9 + a * 4 + 1];
        float tw_ = Os[r][9 + a * 4 + 2];
        float th_ = Os[r][9 + a * 4 + 3];
        float acx = ancs[(size_t)gi * 4 + 0];
        float acy = ancs[(size_t)gi * 4 + 1];
        float aw  = ancs[(size_t)gi * 4 + 2];
        float ah  = ancs[(size_t)gi * 4 + 3];
        float cx = acx + tx_ * aw;
        float cy = acy + ty_ * ah;
        float ww = aw * expf(tw_);
        float hh = ah * expf(th_);
        float x1 = fminf(fmaxf(cx - ww * 0.5f, 0.f), 1.f);
        float y1 = fminf(fmaxf(cy - hh * 0.5f, 0.f), 1.f);
        float x2 = fminf(fmaxf(cx + ww * 0.5f, 0.f), 1.f);
        float y2 = fminf(fmaxf(cy + hh * 0.5f, 0.f), 1.f);
        g_boxes[(size_t)gi * 4 + 0] = x1;
        g_boxes[(size_t)gi * 4 + 1] = y1;
        g_boxes[(size_t)gi * 4 + 2] = x2;
        g_boxes[(size_t)gi * 4 + 3] = y2;
        unsigned sb = __float_as_uint(score);
        g_keys[gi] = ((unsigned long long)sb << 32) | (unsigned long long)(~(unsigned)gi);
    }
}

// ===== selection: exact 64-bit radix select + compact, ONE kernel =====
// 288 co-resident blocks; software grid barrier (last block scans, epoch release).
__global__ __launch_bounds__(256)
void select_all() {
    __shared__ unsigned int sh[256];
    __shared__ unsigned long long s_pref;
    __shared__ int s_last;
    const int tid = threadIdx.x;
    const int gs = gridDim.x * blockDim.x;
    const int gi = blockIdx.x * blockDim.x + tid;
    unsigned myep = 0;

    for (int p = 7; p >= 0; p--) {
        const int shift = p * 8;
        if (tid == 0)
            s_pref = (p == 7) ? 0ull : atomicAdd(&g_prefix, 0ull);
        sh[tid] = 0u;
        __syncthreads();
        const unsigned long long pref = s_pref;
        const unsigned long long mask = (p == 7) ? 0ull : (~0ull << (shift + 8));

        for (int i = gi; i < NBOX; i += gs) {
            unsigned long long k = g_keys[i];
            if (((k ^ pref) & mask) == 0ull)
                atomicAdd(&sh[(unsigned)(k >> shift) & 255u], 1u);
        }
        __syncthreads();
        if (sh[tid]) atomicAdd(&g_hist[tid], sh[tid]);
        __threadfence();
        myep++;

        if (tid == 0)
            s_last = (atomicAdd(&g_bar_count, 1u) == (unsigned)(gridDim.x - 1)) ? 1 : 0;
        __syncthreads();

        if (s_last) {
            // whole last block: gather hist through L2, scan, reset, release
            sh[tid] = atomicAdd(&g_hist[tid], 0u);
            __syncthreads();
            if (tid == 0) {
                int k = atomicAdd(&g_krem, 0);
                int b = 255;
                for (; b >= 0; --b) {
                    int c = (int)sh[b];
                    if (c >= k) break;
                    k -= c;
                }
                if (b < 0) b = 0;
                atomicOr(&g_prefix, ((unsigned long long)(unsigned)b) << shift);
                atomicExch(&g_krem, k);
            }
            atomicExch(&g_hist[tid], 0u);
            __threadfence();
            __syncthreads();
            if (tid == 0) {
                atomicExch(&g_bar_count, 0u);
                __threadfence();
                atomicAdd(&g_epoch, 1u);
            }
        }
        if (tid == 0) {
            while (ld_cg_u32(&g_epoch) < myep) __nanosleep(64);
        }
        __syncthreads();
    }

    // compact: keys >= exact 6000th-largest key (all keys distinct -> exactly 6000)
    if (tid == 0) s_pref = atomicAdd(&g_prefix, 0ull);
    __syncthreads();
    const unsigned long long thr = s_pref;
    for (int i = gi; i < NBOX; i += gs) {
        unsigned long long k = g_keys[i];
        if (k >= thr) {
            int pos = atomicAdd(&g_count, 1);
            if (pos < PRE_NMS) {
                g_ckeys[pos] = k;
                float4 b = *(const float4*)&g_boxes[(size_t)i * 4];
                *(float4*)&g_cboxes[(size_t)pos * 4] = b;
            }
        }
    }
}

// ===== NMS: single block, ALL state in registers, fused suppress+argmax =====
#define NMS_EPT 6   /* 1024 threads x 6 = 6144 >= 6000 */
__global__ __launch_bounds__(1024, 1)
void nms_kernel(float* __restrict__ out) {
    __shared__ unsigned long long s_rk[32];
    __shared__ unsigned int s_rm[32];
    __shared__ unsigned long long s_wkey;
    __shared__ unsigned int s_wmeta;       // (tid<<3)|slot
    __shared__ float4 s_wbox;
    __shared__ float s_wa;

    const int tid = threadIdx.x;
    const int lane = tid & 31;
    const int wid = tid >> 5;
    const int nvalid = min(g_count, PRE_NMS);

    unsigned long long key[NMS_EPT];
    float4 box[NMS_EPT];
    float area[NMS_EPT];
#pragma unroll
    for (int j = 0; j < NMS_EPT; j++) {
        int e = tid + j * 1024;
        if (e < nvalid) {
            key[j] = g_ckeys[e];
            float4 b = *(const float4*)&g_cboxes[(size_t)e * 4];
            box[j] = b;
            area[j] = (b.z - b.x) * (b.w - b.y);
        } else {
            key[j] = 0ull;
            box[j] = make_float4(0.f, 0.f, 0.f, 0.f);
            area[j] = 0.f;
        }
    }

    // ---- initial argmax ----
    {
        unsigned long long bk = 0ull; unsigned bm = 0u;
#pragma unroll
        for (int j = 0; j < NMS_EPT; j++)
            if (key[j] > bk) { bk = key[j]; bm = (unsigned)((tid << 3) | j); }
#pragma unroll
        for (int off = 16; off > 0; off >>= 1) {
            unsigned long long ok = __shfl_down_sync(0xffffffffu, bk, off);
            unsigned om = __shfl_down_sync(0xffffffffu, bm, off);
            if (ok > bk) { bk = ok; bm = om; }
        }
        if (lane == 0) { s_rk[wid] = bk; s_rm[wid] = bm; }
        __syncthreads();
        if (wid == 0) {
            bk = s_rk[lane]; bm = s_rm[lane];
#pragma unroll
            for (int off = 16; off > 0; off >>= 1) {
                unsigned long long ok = __shfl_down_sync(0xffffffffu, bk, off);
                unsigned om = __shfl_down_sync(0xffffffffu, bm, off);
                if (ok > bk) { bk = ok; bm = om; }
            }
            if (lane == 0) { s_wkey = bk; s_wmeta = bm; }
        }
        __syncthreads();
    }

    for (int it = 0; it < POST_NMS; it++) {
        if (s_wkey == 0ull) {
            // no survivors: zero-fill remaining outputs, done
            for (int idx = it * 4 + tid; idx < POST_NMS * 4; idx += 1024)
                out[PROP_OFF + idx] = 0.f;
            return;
        }
        const unsigned wm = s_wmeta;
        if (tid == (int)(wm >> 3)) {
            const int sl = wm & 7;
            s_wbox = box[sl];
            s_wa = area[sl];
            key[sl] = 0ull;              // remove winner
        }
        __syncthreads();   // barrier A: winner box visible

        const float4 wb = s_wbox;
        const float wa = s_wa;
        if (tid == 0) {
            out[PROP_OFF + it * 4 + 0] = wb.x;
            out[PROP_OFF + it * 4 + 1] = wb.y;
            out[PROP_OFF + it * 4 + 2] = wb.z;
            out[PROP_OFF + it * 4 + 3] = wb.w;
        }

        // ---- fused suppression + next argmax (registers only) ----
        unsigned long long bk = 0ull; unsigned bm = 0u;
#pragma unroll
        for (int j = 0; j < NMS_EPT; j++) {
            unsigned long long k = key[j];
            if (k != 0ull) {
                float iw = fminf(wb.z, box[j].z) - fmaxf(wb.x, box[j].x);
                float ih = fminf(wb.w, box[j].w) - fmaxf(wb.y, box[j].y);
                iw = fmaxf(iw, 0.f);
                ih = fmaxf(ih, 0.f);
                float inter = iw * ih;
                float uni = wa + area[j] - inter;
                float p = IOU_THR * uni;
                bool sup;
                if (inter > p * 1.0001f) sup = true;
                else if (inter * 1.0001f < p) sup = false;
                else {
                    float iou = (uni > 0.f) ? inter / uni : 0.f;
                    sup = (iou > IOU_THR);
                }
                if (sup) {
                    key[j] = 0ull;
                } else if (k > bk) {
                    bk = k; bm = (unsigned)((tid << 3) | j);
                }
            }
        }
#pragma unroll
        for (int off = 16; off > 0; off >>= 1) {
            unsigned long long ok = __shfl_down_sync(0xffffffffu, bk, off);
            unsigned om = __shfl_down_sync(0xffffffffu, bm, off);
            if (ok > bk) { bk = ok; bm = om; }
        }
        if (lane == 0) { s_rk[wid] = bk; s_rm[wid] = bm; }
        __syncthreads();   // barrier B
        if (wid == 0) {
            bk = s_rk[lane]; bm = s_rm[lane];
#pragma unroll
            for (int off = 16; off > 0; off >>= 1) {
                unsigned long long ok = __shfl_down_sync(0xffffffffu, bk, off);
                unsigned om = __shfl_down_sync(0xffffffffu, bm, off);
                if (ok > bk) { bk = ok; bm = om; }
            }
            if (lane == 0) { s_wkey = bk; s_wmeta = bm; }
        }
        __syncthreads();   // barrier C
    }
}

// ---------------- launcher ----------------
extern "C" void kernel_launch(void* const* d_in, const int* in_sizes, int n_in,
                              void* d_out, int out_size) {
    const float* feats   = (const float*)d_in[0];
    const float* ancs    = (const float*)d_in[1];
    const float* w_bneck = (const float*)d_in[3];
    const float* b_bneck = (const float*)d_in[4];
    const float* w_cls   = (const float*)d_in[5];
    const float* b_cls   = (const float*)d_in[6];
    const float* w_reg   = (const float*)d_in[7];
    const float* b_reg   = (const float*)d_in[8];
    float* out = (float*)d_out;

    cudaFuncSetAttribute(gemm_bneck_mma, cudaFuncAttributeMaxDynamicSharedMemorySize, GEMM_SMEM);

    gemm_bneck_mma<<<dim3(4, 128), 256, GEMM_SMEM>>>(feats, w_bneck, b_bneck);
    head_kernel<<<M_ROWS / 64, 256>>>(ancs, w_cls, b_cls, w_reg, b_reg, out);
    select_all<<<SEL_BLOCKS, 256>>>();
    nms_kernel<<<1, 1024>>>(out);
}